// round 5
// baseline (speedup 1.0000x reference)
#include <cuda_runtime.h>
#include <math.h>

#define BATCH 16384
#define DIM 64
#define LAMBDA 0.01f
#define TPB 128                         // 4 warps; 16 rows/block (8 lanes per row)
#define GRID (BATCH / 16)               // 1024 blocks -> one full-occupancy wave

__device__ float        g_scratch = 0.0f;
__device__ unsigned int g_count   = 0;

__global__ void __launch_bounds__(TPB) pmf_kernel(
    const int* __restrict__ u,
    const int* __restrict__ iidx,
    const int* __restrict__ s,
    const float4* __restrict__ W4,   // [USER_SIZE * 16]
    const float4* __restrict__ H4,   // [ITEM_SIZE * 16]
    float* __restrict__ out)
{
    const int tid  = threadIdx.x;
    const int grp  = tid >> 3;          // 0..15 (row group within block)
    const int lane = tid & 7;           // 0..7
    const int row  = blockIdx.x * 16 + grp;

    const int ur = __ldg(&u[row]);
    const int ir = __ldg(&iidx[row]);
    const int sv = __ldg(&s[row]);      // broadcast within group, cheap

    // 4 independent 16B gathers per thread (MLP=4): 2 halves of W row, 2 of H row
    const size_t wb = (size_t)ur * 16 + lane;
    const size_t hb = (size_t)ir * 16 + lane;
    const float4 a0 = __ldg(&W4[wb]);
    const float4 a1 = __ldg(&W4[wb + 8]);
    const float4 b0 = __ldg(&H4[hb]);
    const float4 b1 = __ldg(&H4[hb + 8]);

    float dot = a0.x * b0.x + a0.y * b0.y + a0.z * b0.z + a0.w * b0.w
              + a1.x * b1.x + a1.y * b1.y + a1.z * b1.z + a1.w * b1.w;
    float reg = LAMBDA * (a0.x * a0.x + a0.y * a0.y + a0.z * a0.z + a0.w * a0.w
                        + a1.x * a1.x + a1.y * a1.y + a1.z * a1.z + a1.w * a1.w
                        + b0.x * b0.x + b0.y * b0.y + b0.z * b0.z + b0.w * b0.w
                        + b1.x * b1.x + b1.y * b1.y + b1.z * b1.z + b1.w * b1.w);

    // reduce across the 8-lane group
    #pragma unroll
    for (int off = 4; off >= 1; off >>= 1) {
        dot += __shfl_down_sync(0xFFFFFFFFu, dot, off);
        reg += __shfl_down_sync(0xFFFFFFFFu, reg, off);
    }

    __shared__ float sdata[16];
    if (lane == 0) {
        float x  = dot;
        float ls = fminf(x, 0.0f) - log1pf(__expf(-fabsf(x)));  // stable log-sigmoid
        float d  = (float)sv - ls;
        sdata[grp] = d * d + reg;
    }
    __syncthreads();

    if (tid < 16) {
        float v = sdata[tid];
        #pragma unroll
        for (int off = 8; off >= 1; off >>= 1)
            v += __shfl_down_sync(0xFFFFu, v, off);
        if (tid == 0) {
            // release add: partial visible before counter bump; no L1-flushing fence
            asm volatile("red.release.gpu.global.add.f32 [%0], %1;"
                         :: "l"(&g_scratch), "f"(v) : "memory");
            unsigned int old;
            asm volatile("atom.acq_rel.gpu.global.add.u32 %0, [%1], %2;"
                         : "=r"(old) : "l"(&g_count), "r"(1u) : "memory");
            if (old == (unsigned int)(GRID - 1)) {
                unsigned int tot_bits;
                asm volatile("atom.acquire.gpu.global.exch.b32 %0, [%1], %2;"
                             : "=r"(tot_bits) : "l"(&g_scratch), "r"(0u) : "memory");
                g_count = 0;
                out[0] = __int_as_float(tot_bits) * (1.0f / (float)BATCH);
            }
        }
    }
}

extern "C" void kernel_launch(void* const* d_in, const int* in_sizes, int n_in,
                              void* d_out, int out_size) {
    const int*   u = (const int*)d_in[0];
    const int*   i = (const int*)d_in[1];
    const int*   s = (const int*)d_in[2];
    const float* W = (const float*)d_in[3];
    const float* H = (const float*)d_in[4];
    float* out = (float*)d_out;

    pmf_kernel<<<GRID, TPB>>>(u, i, s,
                              (const float4*)W, (const float4*)H, out);
}